// round 14
// baseline (speedup 1.0000x reference)
#include <cuda_runtime.h>
#include <cuda_bf16.h>

// SmoothnessLoss: loss = mean_i( (sHat_i - sY_i)^2 ), i in [0, W), W = N-k-1
// s_i = sum_{j<k} | x[i+j] - mean_j |, k = 64.
// Pair identity: |a-m|+|b-m| = max(|a-b|, |(a+b)-2m|). Windows spaced 2 per
// thread => every window is exactly 32 pairs. THIS ROUND: streaming s/d build
// (volatile 4-chunk load groups, no F[20] array) to eliminate register spills.

#define K_WIN 64
#define BLOCK 256
#define WPT 8
#define SPAN 16                               // window span per thread
#define STRIDE ((BLOCK / 2) * SPAN)           // 2048 windows per block-iter
#define GRID 296                              // 2 blocks/SM x 148 SMs

__device__ float g_partials[GRID];
__device__ unsigned int g_count = 0;

__device__ __forceinline__ float4 ldg4(const float4* p) {
    float4 v;
    asm volatile("ld.global.nc.v4.f32 {%0,%1,%2,%3}, [%4];"
                 : "=f"(v.x), "=f"(v.y), "=f"(v.z), "=f"(v.w) : "l"(p));
    return v;
}

// 8 windows (spacing 2) over elements [eb, eb+80). par in {0,1} selects the
// pairing: pair p = elements (2p+par, 2p+par+1) relative to eb.
// Window j (j=0..7) = pairs [j, j+32).  39 pairs total (p = 0..38).
__device__ __forceinline__ void seg8_pairs(const float4* __restrict__ f4,
                                           int par, float a[WPT])
{
    float s[39], d[39];

    if (par == 0) {
        // pair 2q   = (F[q].x, F[q].y), pair 2q+1 = (F[q].z, F[q].w)
        #pragma unroll
        for (int g = 0; g < 5; g++) {
            float4 c0 = ldg4(f4 + 4 * g + 0);
            float4 c1 = ldg4(f4 + 4 * g + 1);
            float4 c2 = ldg4(f4 + 4 * g + 2);
            float4 c3 = ldg4(f4 + 4 * g + 3);
            const int b = 8 * g;
            s[b+0] = c0.x + c0.y;  d[b+0] = c0.x - c0.y;
            s[b+1] = c0.z + c0.w;  d[b+1] = c0.z - c0.w;
            s[b+2] = c1.x + c1.y;  d[b+2] = c1.x - c1.y;
            s[b+3] = c1.z + c1.w;  d[b+3] = c1.z - c1.w;
            s[b+4] = c2.x + c2.y;  d[b+4] = c2.x - c2.y;
            s[b+5] = c2.z + c2.w;  d[b+5] = c2.z - c2.w;
            s[b+6] = c3.x + c3.y;  d[b+6] = c3.x - c3.y;
            if (b + 7 < 39) { s[b+7] = c3.z + c3.w;  d[b+7] = c3.z - c3.w; }
        }
    } else {
        // pair 2q-1 = (F[q-1].w, F[q].x), pair 2q = (F[q].y, F[q].z)
        float4 c = ldg4(f4);
        s[0] = c.y + c.z;  d[0] = c.y - c.z;
        float pw = c.w;
        #pragma unroll
        for (int g = 0; g < 5; g++) {
            // chunks 4g+1 .. 4g+4 (last group: chunks 17,18,19 only)
            float4 c0 = ldg4(f4 + 4 * g + 1);
            float4 c1 = ldg4(f4 + 4 * g + 2);
            float4 c2 = ldg4(f4 + 4 * g + 3);
            float4 c3;
            if (g < 4) c3 = ldg4(f4 + 4 * g + 4);
            const int b = 8 * g;                     // pair base = 2*(4g+1)-1
            s[b+1] = pw + c0.x;    d[b+1] = pw - c0.x;
            s[b+2] = c0.y + c0.z;  d[b+2] = c0.y - c0.z;
            s[b+3] = c0.w + c1.x;  d[b+3] = c0.w - c1.x;
            s[b+4] = c1.y + c1.z;  d[b+4] = c1.y - c1.z;
            s[b+5] = c1.w + c2.x;  d[b+5] = c1.w - c2.x;
            s[b+6] = c2.y + c2.z;  d[b+6] = c2.y - c2.z;
            if (g < 4) {
                s[b+7] = c2.w + c3.x;  d[b+7] = c2.w - c3.x;
                s[b+8] = c3.y + c3.z;  d[b+8] = c3.y - c3.z;
                pw = c3.w;
            }
        }
    }

    // Window sums from pair sums: sw(0) = sum s[0..31], slide by one pair.
    float q0 = s[0], q1 = s[1], q2 = s[2], q3 = s[3];
    #pragma unroll
    for (int p = 1; p < 8; p++) {
        q0 += s[4*p];
        q1 += s[4*p+1];
        q2 += s[4*p+2];
        q3 += s[4*p+3];
    }
    float sw = (q0 + q1) + (q2 + q3);

    float twoM[WPT];
    #pragma unroll
    for (int j = 0; j < WPT; j++) {
        twoM[j] = sw * (1.0f / 32.0f);        // 2 * mean  (mean = sw/64)
        sw += s[j + 32] - s[j];
    }

    // Pass 2: per window, 32 pairs, 3 instrs each (FADD, FMNMX|.|, FADD).
    #pragma unroll
    for (int j = 0; j < WPT; j++) {
        const float tm = twoM[j];
        float acc0 = 0.0f, acc1 = 0.0f;
        #pragma unroll
        for (int p = j; p < j + 32; p += 2) {
            float t0 = s[p]     - tm;
            float t1 = s[p + 1] - tm;
            acc0 += fmaxf(fabsf(d[p]),     fabsf(t0));
            acc1 += fmaxf(fabsf(d[p + 1]), fabsf(t1));
        }
        a[j] = acc0 + acc1;
    }
}

// Tail fallback: one window, elements p[0..63] (always in-bounds for w < W).
__device__ float window_scalar(const float* __restrict__ p)
{
    float s0 = 0.f, s1 = 0.f, s2 = 0.f, s3 = 0.f;
    #pragma unroll 1
    for (int i = 0; i < K_WIN; i += 4) {
        s0 += p[i]; s1 += p[i+1]; s2 += p[i+2]; s3 += p[i+3];
    }
    const float m = ((s0 + s1) + (s2 + s3)) * (1.0f / (float)K_WIN);
    float t0 = 0.f, t1 = 0.f;
    #pragma unroll 1
    for (int i = 0; i < K_WIN; i += 2) {
        t0 += fabsf(p[i]   - m);
        t1 += fabsf(p[i+1] - m);
    }
    return t0 + t1;
}

__global__ void __launch_bounds__(BLOCK, 2)
smoothness_persist_kernel(const float* __restrict__ yh,
                          const float* __restrict__ yy,
                          int W, int N, int WB,
                          float* __restrict__ out, double invW)
{
    __shared__ float  redf[BLOCK / 32];
    __shared__ double redd[BLOCK / 32];
    __shared__ int    amLast;

    const int tid    = threadIdx.x;
    const int u      = tid >> 1;
    const int par    = tid & 1;
    const int wstart = blockIdx.x * WB;            // multiple of 16
    const int wend   = min(wstart + WB, W);

    float d2 = 0.0f;

    #pragma unroll 1
    for (int g0 = wstart; g0 < wend; g0 += STRIDE) {
        const int eb = g0 + SPAN * u;              // aligned element base (mult of 16)
        const int w0 = eb + par;                   // first window of this thread
        if (w0 >= wend) continue;

        float a1[WPT], a2[WPT];
        if (eb + 80 <= N) {
            seg8_pairs(reinterpret_cast<const float4*>(yh + eb), par, a1);
            seg8_pairs(reinterpret_cast<const float4*>(yy + eb), par, a2);
        } else {
            #pragma unroll 1
            for (int j = 0; j < WPT; j++) {
                const int w = w0 + 2 * j;
                if (w < wend) {
                    a1[j] = window_scalar(yh + w);
                    a2[j] = window_scalar(yy + w);
                } else { a1[j] = 0.0f; a2[j] = 0.0f; }
            }
        }

        #pragma unroll
        for (int j = 0; j < WPT; j++) {
            if (w0 + 2 * j < wend) {
                const float dd = a1[j] - a2[j];
                d2 += dd * dd;
            }
        }
    }

    // Block reduction of d2.
    #pragma unroll
    for (int off = 16; off > 0; off >>= 1)
        d2 += __shfl_down_sync(0xffffffffu, d2, off);

    const int lane = tid & 31, wid = tid >> 5;
    if (lane == 0) redf[wid] = d2;
    __syncthreads();
    if (wid == 0) {
        float vv = (lane < BLOCK / 32) ? redf[lane] : 0.0f;
        #pragma unroll
        for (int off = 4; off > 0; off >>= 1)
            vv += __shfl_down_sync(0xffffffffu, vv, off);
        if (lane == 0) {
            g_partials[blockIdx.x] = vv;
            __threadfence();
            unsigned int c = atomicAdd(&g_count, 1u);
            amLast = (c == (unsigned int)(gridDim.x - 1));
        }
    }
    __syncthreads();

    if (amLast) {
        // Deterministic final reduction (fixed order/topology).
        double sd = 0.0;
        #pragma unroll 1
        for (int i = tid; i < GRID; i += BLOCK)
            sd += (double)g_partials[i];
        #pragma unroll
        for (int off = 16; off > 0; off >>= 1)
            sd += __shfl_down_sync(0xffffffffu, sd, off);
        if (lane == 0) redd[wid] = sd;
        __syncthreads();
        if (wid == 0) {
            double vv = (lane < BLOCK / 32) ? redd[lane] : 0.0;
            #pragma unroll
            for (int off = 4; off > 0; off >>= 1)
                vv += __shfl_down_sync(0xffffffffu, vv, off);
            if (lane == 0) {
                out[0] = (float)(vv * invW);
                g_count = 0;                 // reset for next graph replay
            }
        }
    }
}

extern "C" void kernel_launch(void* const* d_in, const int* in_sizes, int n_in,
                              void* d_out, int out_size)
{
    const float* yh = (const float*)d_in[0];
    const float* yy = (const float*)d_in[1];
    const int N = in_sizes[0];
    const int W = N - K_WIN - 1;
    int WB = (W + GRID - 1) / GRID;
    WB = (WB + 15) & ~15;                        // multiple of 16 (SPAN/alignment)

    smoothness_persist_kernel<<<GRID, BLOCK>>>(yh, yy, W, N, WB,
                                               (float*)d_out, 1.0 / (double)W);
}